// round 1
// baseline (speedup 1.0000x reference)
#include <cuda_runtime.h>

#define BB 8
#define LL 4096
#define DM 512
#define HH 8
#define DD 64
#define UU 45
#define NCH 16
#define CHUNK (LL / NCH)
#define SCALE 0.125f

// ---------------- scratch (static device globals; no allocs allowed) ----------------
__device__ float g_Q[BB * HH * LL * DD];
__device__ float g_K[BB * HH * LL * DD];
__device__ float g_V[BB * HH * LL * DD];
__device__ float g_M[BB * HH * LL];
__device__ int   g_top[BB * HH * UU];
__device__ float g_meanV[BB * HH * DD];
__device__ float g_base[BB * DM];
__device__ float g_pm[BB * HH * NCH * UU];
__device__ float g_pl[BB * HH * NCH * UU];
__device__ float g_pacc[BB * HH * NCH * UU * DD];
__device__ float g_attn[BB * HH * UU * DD];

// ---------------- projection GEMM: C(BL x 512) = A x W + bias, scatter to (B,H,L,D) --------
__global__ __launch_bounds__(256) void proj_kernel(
    const float* __restrict__ A, const float* __restrict__ W,
    const float* __restrict__ bias, int which)
{
    float* P = (which == 0) ? g_Q : (which == 1) ? g_K : g_V;
    __shared__ float As[8][128];
    __shared__ float Bs[8][128];
    int tid = threadIdx.x;
    int m0 = blockIdx.y * 128, n0 = blockIdx.x * 128;
    int tm = (tid >> 4) << 3;          // 0..120
    int tn = (tid & 15) << 3;          // 0..120
    int arow = tid >> 1, acol = (tid & 1) << 2;
    int brow = tid >> 5, bcol = (tid & 31) << 2;

    float acc[8][8];
#pragma unroll
    for (int i = 0; i < 8; i++)
#pragma unroll
        for (int j = 0; j < 8; j++) acc[i][j] = 0.f;

    const float* Aptr = A + (size_t)(m0 + arow) * DM + acol;
    const float* Wptr = W + (size_t)brow * DM + n0 + bcol;

    for (int k0 = 0; k0 < DM; k0 += 8) {
        float4 av = *(const float4*)(Aptr + k0);
        float4 bv = *(const float4*)(Wptr + (size_t)k0 * DM);
        __syncthreads();
        As[acol + 0][arow] = av.x;
        As[acol + 1][arow] = av.y;
        As[acol + 2][arow] = av.z;
        As[acol + 3][arow] = av.w;
        *(float4*)&Bs[brow][bcol] = bv;
        __syncthreads();
#pragma unroll
        for (int kk = 0; kk < 8; kk++) {
            float a[8], b[8];
            *(float4*)a       = *(float4*)&As[kk][tm];
            *(float4*)(a + 4) = *(float4*)&As[kk][tm + 4];
            *(float4*)b       = *(float4*)&Bs[kk][tn];
            *(float4*)(b + 4) = *(float4*)&Bs[kk][tn + 4];
#pragma unroll
            for (int i = 0; i < 8; i++)
#pragma unroll
                for (int j = 0; j < 8; j++) acc[i][j] += a[i] * b[j];
        }
    }

    int n_base = n0 + tn;
    int h = n_base >> 6, d0 = n_base & 63;
    float bj[8];
#pragma unroll
    for (int j = 0; j < 8; j++) bj[j] = bias[n_base + j];
#pragma unroll
    for (int i = 0; i < 8; i++) {
        int m = m0 + tm + i;
        int b = m >> 12, l = m & (LL - 1);
        float* row = P + ((size_t)(b * HH + h) * LL + l) * DD + d0;
        float4 v0, v1;
        v0.x = acc[i][0] + bj[0]; v0.y = acc[i][1] + bj[1];
        v0.z = acc[i][2] + bj[2]; v0.w = acc[i][3] + bj[3];
        v1.x = acc[i][4] + bj[4]; v1.y = acc[i][5] + bj[5];
        v1.z = acc[i][6] + bj[6]; v1.w = acc[i][7] + bj[7];
        *(float4*)(row)     = v0;
        *(float4*)(row + 4) = v1;
    }
}

// ---------------- sampled scoring -> M = max - mean over 45 sampled keys ----------------
__global__ __launch_bounds__(256) void score_kernel(const int* __restrict__ sidx)
{
    __shared__ float Ks[UU * DD];
    __shared__ int ssi[UU];
    int bh = blockIdx.x;
    int tid = threadIdx.x;
    if (tid < UU) ssi[tid] = sidx[tid];
    __syncthreads();
    for (int i = tid; i < UU * DD; i += 256) {
        int j = i >> 6, d = i & 63;
        Ks[i] = g_K[((size_t)bh * LL + ssi[j]) * DD + d];
    }
    __syncthreads();

    int qi = tid >> 1, half = tid & 1;
    int l = blockIdx.y * 128 + qi;
    const float* qrow = g_Q + ((size_t)bh * LL + l) * DD + half * 32;
    float4 q4[8];
#pragma unroll
    for (int i = 0; i < 8; i++) q4[i] = *(const float4*)(qrow + 4 * i);

    float mx = -1e30f, sm = 0.f;
    for (int j = 0; j < UU; j++) {
        const float* kr = Ks + j * DD + half * 32;
        float s = 0.f;
#pragma unroll
        for (int i = 0; i < 8; i++) {
            float4 k4 = *(const float4*)(kr + 4 * i);
            s += q4[i].x * k4.x + q4[i].y * k4.y + q4[i].z * k4.z + q4[i].w * k4.w;
        }
        s += __shfl_xor_sync(0xffffffffu, s, 1);
        mx = fmaxf(mx, s);
        sm += s;
    }
    if (half == 0)
        g_M[(size_t)bh * LL + l] = (mx - sm * (1.f / UU)) * SCALE;
}

// ---------------- top-45 selection per (b,h) ----------------
__global__ __launch_bounds__(256) void topk_kernel()
{
    __shared__ float vals[LL];
    __shared__ float rv[256];
    __shared__ int ri[256];
    int bh = blockIdx.x, tid = threadIdx.x;
    for (int i = tid; i < LL; i += 256) vals[i] = g_M[(size_t)bh * LL + i];
    __syncthreads();
    for (int it = 0; it < UU; it++) {
        float bv = -1e38f; int bi = 0x7fffffff;
        for (int i = tid; i < LL; i += 256) {
            float v = vals[i];
            if (v > bv) { bv = v; bi = i; }
        }
        rv[tid] = bv; ri[tid] = bi;
        __syncthreads();
        for (int s = 128; s > 0; s >>= 1) {
            if (tid < s) {
                float v2 = rv[tid + s]; int i2 = ri[tid + s];
                if (v2 > rv[tid] || (v2 == rv[tid] && i2 < ri[tid])) {
                    rv[tid] = v2; ri[tid] = i2;
                }
            }
            __syncthreads();
        }
        if (tid == 0) {
            g_top[bh * UU + it] = ri[0];
            vals[ri[0]] = -1e38f;
        }
        __syncthreads();
    }
}

// ---------------- mean(V) over L per (b,h,d) ----------------
__global__ __launch_bounds__(256) void meanv_kernel()
{
    __shared__ float red[4][64];
    int bh = blockIdx.x, tid = threadIdx.x;
    int d = tid & 63, part = tid >> 6;
    const float* base = g_V + ((size_t)bh * LL + part * (LL / 4)) * DD + d;
    float s0 = 0.f, s1 = 0.f, s2 = 0.f, s3 = 0.f;
    for (int i = 0; i < LL / 4; i += 4) {
        s0 += base[(size_t)(i + 0) * DD];
        s1 += base[(size_t)(i + 1) * DD];
        s2 += base[(size_t)(i + 2) * DD];
        s3 += base[(size_t)(i + 3) * DD];
    }
    red[part][d] = (s0 + s1) + (s2 + s3);
    __syncthreads();
    if (part == 0)
        g_meanV[bh * DD + d] =
            (red[0][d] + red[1][d] + red[2][d] + red[3][d]) * (1.f / LL);
}

// ---------------- base row per batch: concat(meanV) @ Wo + bo ----------------
__global__ __launch_bounds__(512) void base_kernel(const float* __restrict__ Wo,
                                                   const float* __restrict__ bo)
{
    int b = blockIdx.x, c = threadIdx.x;
    float acc = bo[c];
    const float* mv = g_meanV + b * DM;
    for (int k = 0; k < DM; k++) acc += mv[k] * Wo[(size_t)k * DM + c];
    g_base[b * DM + c] = acc;
}

// ---------------- flash attention for top-45 queries, split over NCH L-chunks ----------------
__global__ __launch_bounds__(384) void att_kernel()
{
    __shared__ float Qs[UU * 64];
    __shared__ float Ks[64 * 68];   // padded stride (68) -> conflict-free row reads
    __shared__ float Vs[64 * 64];
    int bh = blockIdx.x, ch = blockIdx.y;
    int tid = threadIdx.x;
    int q = tid >> 3, lane8 = tid & 7;
    int qe = (q < UU) ? q : (UU - 1);

    for (int i = tid; i < UU * 64; i += 384) {
        int qq = i >> 6, d = i & 63;
        int l = g_top[bh * UU + qq];
        Qs[i] = g_Q[((size_t)bh * LL + l) * DD + d];
    }
    __syncthreads();

    float4 q4[16];
#pragma unroll
    for (int dd = 0; dd < 16; dd++) q4[dd] = *(const float4*)(Qs + qe * 64 + dd * 4);

    float m = -1e30f, lsum = 0.f;
    float acc[8];
#pragma unroll
    for (int i = 0; i < 8; i++) acc[i] = 0.f;

    int key0 = ch * CHUNK;
    for (int t0 = 0; t0 < CHUNK; t0 += 64) {
        __syncthreads();
        for (int i = tid; i < 1024; i += 384) {   // 64x64 floats as float4
            int r = i >> 4, c4 = (i & 15) << 2;
            size_t gidx = ((size_t)bh * LL + key0 + t0 + r) * DD + c4;
            *(float4*)&Ks[r * 68 + c4] = *(const float4*)&g_K[gidx];
            *(float4*)&Vs[r * 64 + c4] = *(const float4*)&g_V[gidx];
        }
        __syncthreads();

        // lane owns keys j = lane8 + 8*tt (interleaved -> bank-conflict-free)
        float s[8];
#pragma unroll
        for (int tt = 0; tt < 8; tt++) {
            int j = lane8 + 8 * tt;
            const float* kr = Ks + j * 68;
            float sv = 0.f;
#pragma unroll
            for (int dd = 0; dd < 16; dd++) {
                float4 kv = *(const float4*)(kr + dd * 4);
                sv += q4[dd].x * kv.x + q4[dd].y * kv.y +
                      q4[dd].z * kv.z + q4[dd].w * kv.w;
            }
            s[tt] = sv * SCALE;
        }
        float tmax = s[0];
#pragma unroll
        for (int tt = 1; tt < 8; tt++) tmax = fmaxf(tmax, s[tt]);
#pragma unroll
        for (int off = 4; off; off >>= 1)
            tmax = fmaxf(tmax, __shfl_xor_sync(0xffffffffu, tmax, off));
        float mnew = fmaxf(m, tmax);
        float alpha = __expf(m - mnew);
        lsum *= alpha;
#pragma unroll
        for (int i = 0; i < 8; i++) acc[i] *= alpha;
        float p[8];
#pragma unroll
        for (int tt = 0; tt < 8; tt++) {
            p[tt] = __expf(s[tt] - mnew);
            lsum += p[tt];
        }
        m = mnew;
#pragma unroll
        for (int j = 0; j < 64; j++) {
            float pj = __shfl_sync(0xffffffffu, p[j >> 3], j & 7, 8);
            const float* vr = Vs + j * 64 + lane8 * 8;
            float4 v0 = *(const float4*)vr;
            float4 v1 = *(const float4*)(vr + 4);
            acc[0] += pj * v0.x; acc[1] += pj * v0.y;
            acc[2] += pj * v0.z; acc[3] += pj * v0.w;
            acc[4] += pj * v1.x; acc[5] += pj * v1.y;
            acc[6] += pj * v1.z; acc[7] += pj * v1.w;
        }
    }
#pragma unroll
    for (int off = 4; off; off >>= 1)
        lsum += __shfl_xor_sync(0xffffffffu, lsum, off);

    if (q < UU) {
        int idx = (bh * NCH + ch) * UU + q;
        if (lane8 == 0) { g_pm[idx] = m; g_pl[idx] = lsum; }
        float* pa = g_pacc + (size_t)idx * DD + lane8 * 8;
#pragma unroll
        for (int i = 0; i < 8; i++) pa[i] = acc[i];
    }
}

// ---------------- merge split-L partials ----------------
__global__ __launch_bounds__(64) void combine_kernel()
{
    int r = blockIdx.x;             // bh*UU + q
    int d = threadIdx.x;
    int bh = r / UU, q = r % UU;
    float M = -1e30f;
#pragma unroll
    for (int c = 0; c < NCH; c++)
        M = fmaxf(M, g_pm[(bh * NCH + c) * UU + q]);
    float Ltot = 0.f, acc = 0.f;
#pragma unroll
    for (int c = 0; c < NCH; c++) {
        int idx = (bh * NCH + c) * UU + q;
        float e = __expf(g_pm[idx] - M);
        Ltot += g_pl[idx] * e;
        acc  += e * g_pacc[(size_t)idx * DD + d];
    }
    g_attn[(size_t)(bh * UU + q) * DD + d] = acc / Ltot;
}

// ---------------- final output: broadcast base row + rank-64 head corrections ----------------
__global__ __launch_bounds__(128) void final_kernel(const float* __restrict__ Wo,
                                                    float* __restrict__ out)
{
    __shared__ int s_hits[HH];
    __shared__ float delta[64];
    int qrow = blockIdx.x, b = blockIdx.y;
    int tid = threadIdx.x;
    int c0 = tid * 4;

    if (tid < HH) s_hits[tid] = -1;
    __syncthreads();
    if (tid < UU) {
#pragma unroll
        for (int h = 0; h < HH; h++)
            if (g_top[(b * HH + h) * UU + tid] == qrow) s_hits[h] = tid;
    }
    __syncthreads();

    float4 acc = *(const float4*)&g_base[b * DM + c0];
    for (int h = 0; h < HH; h++) {
        int hit = s_hits[h];
        if (hit >= 0) {
            if (tid < 64)
                delta[tid] = g_attn[((size_t)(b * HH + h) * UU + hit) * DD + tid] -
                             g_meanV[(b * HH + h) * DD + tid];
            __syncthreads();
#pragma unroll 4
            for (int d = 0; d < 64; d++) {
                float dv = delta[d];
                float4 w = *(const float4*)&Wo[(size_t)(h * 64 + d) * DM + c0];
                acc.x += dv * w.x; acc.y += dv * w.y;
                acc.z += dv * w.z; acc.w += dv * w.w;
            }
            __syncthreads();
        }
    }
    *(float4*)&out[((size_t)b * LL + qrow) * DM + c0] = acc;
}

// ---------------- launcher ----------------
extern "C" void kernel_launch(void* const* d_in, const int* in_sizes, int n_in,
                              void* d_out, int out_size)
{
    const float* queries = (const float*)d_in[0];
    const float* keys    = (const float*)d_in[1];
    const float* values  = (const float*)d_in[2];
    const int*   sidx    = (const int*)d_in[3];
    const float* Wq = (const float*)d_in[4];
    const float* bq = (const float*)d_in[5];
    const float* Wk = (const float*)d_in[6];
    const float* bk = (const float*)d_in[7];
    const float* Wv = (const float*)d_in[8];
    const float* bv = (const float*)d_in[9];
    const float* Wo = (const float*)d_in[10];
    const float* bo = (const float*)d_in[11];
    float* out = (float*)d_out;

    dim3 gproj(DM / 128, (BB * LL) / 128);
    proj_kernel<<<gproj, 256>>>(queries, Wq, bq, 0);
    proj_kernel<<<gproj, 256>>>(keys,    Wk, bk, 1);
    proj_kernel<<<gproj, 256>>>(values,  Wv, bv, 2);

    score_kernel<<<dim3(BB * HH, LL / 128), 256>>>(sidx);
    topk_kernel<<<BB * HH, 256>>>();
    meanv_kernel<<<BB * HH, 256>>>();
    base_kernel<<<BB, 512>>>(Wo, bo);
    att_kernel<<<dim3(BB * HH, NCH), 384>>>();
    combine_kernel<<<BB * HH * UU, 64>>>();
    final_kernel<<<dim3(LL, BB), 128>>>(Wo, out);
}

// round 3
// speedup vs baseline: 1.8622x; 1.8622x over previous
#include <cuda_runtime.h>
#include <cuda_bf16.h>
#include <cstdint>

#define BB 8
#define LL 4096
#define DM 512
#define HH 8
#define DD 64
#define UU 45
#define NCH 16
#define CHUNK (LL / NCH)
#define SCALE 0.125f
#define BL (BB * LL)

// ---------------- scratch (static device globals; no allocs allowed) ----------------
__device__ float g_Q[BB * HH * LL * DD];
__device__ float g_K[BB * HH * LL * DD];
__device__ float g_V[BB * HH * LL * DD];
__device__ float g_M[BB * HH * LL];
__device__ int   g_top[BB * HH * UU];
__device__ float g_meanV[BB * HH * DD];
__device__ float g_base[BB * DM];
__device__ float g_pm[BB * HH * NCH * UU];
__device__ float g_pl[BB * HH * NCH * UU];
__device__ float g_pacc[BB * HH * NCH * UU * DD];
__device__ float g_attn[BB * HH * UU * DD];
__device__ __nv_bfloat16 g_Wth[3][DM * DM];   // W transposed [n][k], hi bf16
__device__ __nv_bfloat16 g_Wtl[3][DM * DM];   // W transposed [n][k], lo bf16
__device__ __nv_bfloat16 g_Ah[3][BL * DM];    // activations hi bf16
__device__ __nv_bfloat16 g_Al[3][BL * DM];    // activations lo bf16

// ================= PTX helpers (sm_80-era, legal on sm_103 base) =================
__device__ __forceinline__ uint32_t smem_u32(const void* p) {
    uint32_t a;
    asm("{ .reg .u64 t; cvta.to.shared.u64 t, %1; cvt.u32.u64 %0, t; }"
        : "=r"(a) : "l"(p));
    return a;
}
#define SWZ128(off)   ((off) ^ (((off) >> 3) & 0x70))

#define CP_ASYNC16(dst, src) \
    asm volatile("cp.async.cg.shared.global [%0], [%1], 16;" :: "r"(dst), "l"(src))
#define CP_COMMIT() asm volatile("cp.async.commit_group;" ::: "memory")
#define CP_WAIT(n)  asm volatile("cp.async.wait_group %0;" :: "n"(n) : "memory")

__device__ __forceinline__ void ldsm_x4(uint32_t* r, uint32_t addr) {
    asm volatile("ldmatrix.sync.aligned.m8n8.x4.shared.b16 {%0,%1,%2,%3}, [%4];"
        : "=r"(r[0]), "=r"(r[1]), "=r"(r[2]), "=r"(r[3]) : "r"(addr));
}
__device__ __forceinline__ void mma16816(float* d, const uint32_t* a,
                                         const uint32_t* b, const float* c) {
    asm volatile(
        "mma.sync.aligned.m16n8k16.row.col.f32.bf16.bf16.f32 "
        "{%0,%1,%2,%3},{%4,%5,%6,%7},{%8,%9},{%10,%11,%12,%13};"
        : "=f"(d[0]), "=f"(d[1]), "=f"(d[2]), "=f"(d[3])
        : "r"(a[0]), "r"(a[1]), "r"(a[2]), "r"(a[3]),
          "r"(b[0]), "r"(b[1]),
          "f"(c[0]), "f"(c[1]), "f"(c[2]), "f"(c[3]));
}

// smem stage layout: 4 tiles of 128x64 bf16 (16KB each), 2 stages
#define T_AH 0
#define T_AL 16384
#define T_WH 32768
#define T_WL 49152
#define STAGE_SZ 65536
#define OFF_BIAS 131072
#define DYN_SMEM (131072 + 1024)

// ---------------- W prep: transpose + split to bf16 hi/lo ----------------
__global__ __launch_bounds__(256) void prep_w(const float* __restrict__ Wq,
                                              const float* __restrict__ Wk,
                                              const float* __restrict__ Wv)
{
    int which = blockIdx.y;
    const float* W = (which == 0) ? Wq : (which == 1) ? Wk : Wv;
    int idx = (blockIdx.x * 256 + threadIdx.x) * 4;   // 4 consecutive k for fixed n
    int n = idx >> 9, k = idx & 511;
#pragma unroll
    for (int i = 0; i < 4; i++) {
        float x = W[(size_t)(k + i) * DM + n];
        __nv_bfloat16 hb = __float2bfloat16(x);
        g_Wth[which][(size_t)n * DM + k + i] = hb;
        g_Wtl[which][(size_t)n * DM + k + i] = __float2bfloat16(x - __bfloat162float(hb));
    }
}

// ---------------- activation split: fp32 -> bf16 hi/lo ----------------
__global__ __launch_bounds__(256) void split_act(const float* __restrict__ q,
                                                 const float* __restrict__ k,
                                                 const float* __restrict__ v)
{
    int which = blockIdx.y;
    const float* A = (which == 0) ? q : (which == 1) ? k : v;
    size_t i0 = ((size_t)blockIdx.x * 256 + threadIdx.x) * 8;
    float4 f0 = *(const float4*)(A + i0);
    float4 f1 = *(const float4*)(A + i0 + 4);
    float xs[8] = {f0.x, f0.y, f0.z, f0.w, f1.x, f1.y, f1.z, f1.w};
    __align__(16) __nv_bfloat16 h[8], l[8];
#pragma unroll
    for (int i = 0; i < 8; i++) {
        __nv_bfloat16 hb = __float2bfloat16(xs[i]);
        h[i] = hb;
        l[i] = __float2bfloat16(xs[i] - __bfloat162float(hb));
    }
    *(uint4*)&g_Ah[which][i0] = *(uint4*)h;
    *(uint4*)&g_Al[which][i0] = *(uint4*)l;
}

// ---------------- split-bf16 mma.sync GEMM: P = A x W + bias ----------------
__global__ __launch_bounds__(256) void proj_mma(
    const float* __restrict__ bq, const float* __restrict__ bk,
    const float* __restrict__ bv)
{
    extern __shared__ char dsm[];
    int which = blockIdx.z;
    float* P = (which == 0) ? g_Q : (which == 1) ? g_K : g_V;
    const float* bias = (which == 0) ? bq : (which == 1) ? bk : bv;
    const __nv_bfloat16* Ah = g_Ah[which];
    const __nv_bfloat16* Al = g_Al[which];
    const __nv_bfloat16* Wh = g_Wth[which];
    const __nv_bfloat16* Wl = g_Wtl[which];

    uint32_t su = smem_u32(dsm);
    int tid = threadIdx.x;
    int lane = tid & 31, wid = tid >> 5;
    int wm = wid & 3, wn = wid >> 2;          // warp: 32 M x 64 N
    int m0 = blockIdx.y * 128, n0 = blockIdx.x * 128;

    // bias slice -> smem
    float* bias_s = (float*)(dsm + OFF_BIAS);
    if (tid < 128) bias_s[tid] = bias[n0 + tid];

    float acc[2][8][4];
#pragma unroll
    for (int a = 0; a < 2; a++)
#pragma unroll
        for (int b = 0; b < 8; b++)
#pragma unroll
            for (int c = 0; c < 4; c++) acc[a][b][c] = 0.f;

    // --------- stage loader (cp.async) ---------
    auto load_stage = [&](int stage, int k0) {
        uint32_t sb = su + stage * STAGE_SZ;
#pragma unroll
        for (int t = 0; t < 4; t++) {
            int idx = tid + 256 * t;          // [0,1024)
            int r = idx >> 3, c = idx & 7;
            uint32_t sw = SWZ128((uint32_t)(r * 128 + c * 16));
            const __nv_bfloat16* asrc = Ah + (size_t)(m0 + r) * DM + k0 + c * 8;
            const __nv_bfloat16* lsrc = Al + (size_t)(m0 + r) * DM + k0 + c * 8;
            const __nv_bfloat16* wsrc = Wh + (size_t)(n0 + r) * DM + k0 + c * 8;
            const __nv_bfloat16* msrc = Wl + (size_t)(n0 + r) * DM + k0 + c * 8;
            CP_ASYNC16(sb + T_AH + sw, asrc);
            CP_ASYNC16(sb + T_AL + sw, lsrc);
            CP_ASYNC16(sb + T_WH + sw, wsrc);
            CP_ASYNC16(sb + T_WL + sw, msrc);
        }
        CP_COMMIT();
    };

    load_stage(0, 0);

    for (int chunk = 0; chunk < 8; chunk++) {
        if (chunk < 7) load_stage((chunk + 1) & 1, (chunk + 1) * 64);
        if (chunk < 7) { CP_WAIT(1); } else { CP_WAIT(0); }
        __syncthreads();

        uint32_t sb = su + (chunk & 1) * STAGE_SZ;
#pragma unroll
        for (int p = 0; p < 3; p++) {
            uint32_t At = sb + ((p == 2) ? T_AL : T_AH);
            uint32_t Bt = sb + ((p == 1) ? T_WL : T_WH);
#pragma unroll
            for (int ks = 0; ks < 4; ks++) {
                uint32_t breg[16];
#pragma unroll
                for (int g2 = 0; g2 < 4; g2++) {
                    int grp = lane >> 3;
                    int row = wn * 64 + g2 * 16 + ((grp >> 1) << 3) + (lane & 7);
                    int kb = ks * 32 + ((grp & 1) << 4);
                    ldsm_x4(&breg[g2 * 4], Bt + SWZ128((uint32_t)(row * 128 + kb)));
                }
                uint32_t areg[2][4];
#pragma unroll
                for (int mf = 0; mf < 2; mf++) {
                    int row = wm * 32 + mf * 16 + (lane & 15);
                    int kb = ks * 32 + ((lane >> 4) << 4);
                    ldsm_x4(areg[mf], At + SWZ128((uint32_t)(row * 128 + kb)));
                }
#pragma unroll
                for (int mf = 0; mf < 2; mf++)
#pragma unroll
                    for (int nf = 0; nf < 8; nf++)
                        mma16816(acc[mf][nf], areg[mf], &breg[nf * 2], acc[mf][nf]);
            }
        }
        __syncthreads();
    }

    // --------- epilogue: frags -> smem (stride 132) -> coalesced scatter ---------
    float* Cs = (float*)dsm;
#pragma unroll
    for (int mf = 0; mf < 2; mf++)
#pragma unroll
        for (int nf = 0; nf < 8; nf++) {
            int r = wm * 32 + mf * 16 + (lane >> 2);
            int col = wn * 64 + nf * 8 + (lane & 3) * 2;
            Cs[r * 132 + col]           = acc[mf][nf][0] + bias_s[col];
            Cs[r * 132 + col + 1]       = acc[mf][nf][1] + bias_s[col + 1];
            Cs[(r + 8) * 132 + col]     = acc[mf][nf][2] + bias_s[col];
            Cs[(r + 8) * 132 + col + 1] = acc[mf][nf][3] + bias_s[col + 1];
        }
    __syncthreads();

#pragma unroll
    for (int it = 0; it < 16; it++) {
        int idx = tid + it * 256;            // [0,4096) float4 slots
        int row = idx >> 5, c4 = idx & 31;
        int m = m0 + row;
        int b = m >> 12, l = m & (LL - 1);
        int n = n0 + c4 * 4;
        int h = n >> 6, d = n & 63;
        float4 v;
        v.x = Cs[row * 132 + c4 * 4 + 0];
        v.y = Cs[row * 132 + c4 * 4 + 1];
        v.z = Cs[row * 132 + c4 * 4 + 2];
        v.w = Cs[row * 132 + c4 * 4 + 3];
        *(float4*)&P[((size_t)(b * HH + h) * LL + l) * DD + d] = v;
    }
}

// ---------------- sampled scoring -> M = max - mean over 45 sampled keys ----------------
__global__ __launch_bounds__(256) void score_kernel(const int* __restrict__ sidx)
{
    __shared__ float Ks[UU * DD];
    __shared__ int ssi[UU];
    int bh = blockIdx.x;
    int tid = threadIdx.x;
    if (tid < UU) ssi[tid] = sidx[tid];
    __syncthreads();
    for (int i = tid; i < UU * DD; i += 256) {
        int j = i >> 6, d = i & 63;
        Ks[i] = g_K[((size_t)bh * LL + ssi[j]) * DD + d];
    }
    __syncthreads();

    int qi = tid >> 1, half = tid & 1;
    int l = blockIdx.y * 128 + qi;
    const float* qrow = g_Q + ((size_t)bh * LL + l) * DD + half * 32;
    float4 q4[8];
#pragma unroll
    for (int i = 0; i < 8; i++) q4[i] = *(const float4*)(qrow + 4 * i);

    float mx = -1e30f, sm = 0.f;
    for (int j = 0; j < UU; j++) {
        const float* kr = Ks + j * DD + half * 32;
        float s = 0.f;
#pragma unroll
        for (int i = 0; i < 8; i++) {
            float4 k4 = *(const float4*)(kr + 4 * i);
            s += q4[i].x * k4.x + q4[i].y * k4.y + q4[i].z * k4.z + q4[i].w * k4.w;
        }
        s += __shfl_xor_sync(0xffffffffu, s, 1);
        mx = fmaxf(mx, s);
        sm += s;
    }
    if (half == 0)
        g_M[(size_t)bh * LL + l] = (mx - sm * (1.f / UU)) * SCALE;
}

// ---------------- top-45 selection per (b,h) ----------------
__global__ __launch_bounds__(256) void topk_kernel()
{
    __shared__ float vals[LL];
    __shared__ float rv[256];
    __shared__ int ri[256];
    int bh = blockIdx.x, tid = threadIdx.x;
    for (int i = tid; i < LL; i += 256) vals[i] = g_M[(size_t)bh * LL + i];
    __syncthreads();
    for (int it = 0; it < UU; it++) {
        float bv = -1e38f; int bi = 0x7fffffff;
        for (int i = tid; i < LL; i += 256) {
            float v = vals[i];
            if (v > bv) { bv = v; bi = i; }
        }
        rv[tid] = bv; ri[tid] = bi;
        __syncthreads();
        for (int s = 128; s > 0; s >>= 1) {
            if (tid < s) {
                float v2 = rv[tid + s]; int i2 = ri[tid + s];
                if (v2 > rv[tid] || (v2 == rv[tid] && i2 < ri[tid])) {
                    rv[tid] = v2; ri[tid] = i2;
                }
            }
            __syncthreads();
        }
        if (tid == 0) {
            g_top[bh * UU + it] = ri[0];
            vals[ri[0]] = -1e38f;
        }
        __syncthreads();
    }
}

// ---------------- mean(V) over L per (b,h,d) ----------------
__global__ __launch_bounds__(256) void meanv_kernel()
{
    __shared__ float red[4][64];
    int bh = blockIdx.x, tid = threadIdx.x;
    int d = tid & 63, part = tid >> 6;
    const float* base = g_V + ((size_t)bh * LL + part * (LL / 4)) * DD + d;
    float s0 = 0.f, s1 = 0.f, s2 = 0.f, s3 = 0.f;
    for (int i = 0; i < LL / 4; i += 4) {
        s0 += base[(size_t)(i + 0) * DD];
        s1 += base[(size_t)(i + 1) * DD];
        s2 += base[(size_t)(i + 2) * DD];
        s3 += base[(size_t)(i + 3) * DD];
    }
    red[part][d] = (s0 + s1) + (s2 + s3);
    __syncthreads();
    if (part == 0)
        g_meanV[bh * DD + d] =
            (red[0][d] + red[1][d] + red[2][d] + red[3][d]) * (1.f / LL);
}

// ---------------- base row per batch: concat(meanV) @ Wo + bo ----------------
__global__ __launch_bounds__(512) void base_kernel(const float* __restrict__ Wo,
                                                   const float* __restrict__ bo)
{
    int b = blockIdx.x, c = threadIdx.x;
    float acc = bo[c];
    const float* mv = g_meanV + b * DM;
    for (int k = 0; k < DM; k++) acc += mv[k] * Wo[(size_t)k * DM + c];
    g_base[b * DM + c] = acc;
}

// ---------------- flash attention for top-45 queries, split over NCH L-chunks ----------------
__global__ __launch_bounds__(384) void att_kernel()
{
    __shared__ float Qs[UU * 64];
    __shared__ float Ks[64 * 68];
    __shared__ float Vs[64 * 64];
    int bh = blockIdx.x, ch = blockIdx.y;
    int tid = threadIdx.x;
    int q = tid >> 3, lane8 = tid & 7;
    int qe = (q < UU) ? q : (UU - 1);

    for (int i = tid; i < UU * 64; i += 384) {
        int qq = i >> 6, d = i & 63;
        int l = g_top[bh * UU + qq];
        Qs[i] = g_Q[((size_t)bh * LL + l) * DD + d];
    }
    __syncthreads();

    float4 q4[16];
#pragma unroll
    for (int dd = 0; dd < 16; dd++) q4[dd] = *(const float4*)(Qs + qe * 64 + dd * 4);

    float m = -1e30f, lsum = 0.f;
    float acc[8];
#pragma unroll
    for (int i = 0; i < 8; i++) acc[i] = 0.f;

    int key0 = ch * CHUNK;
    for (int t0 = 0; t0 < CHUNK; t0 += 64) {
        __syncthreads();
        for (int i = tid; i < 1024; i += 384) {
            int r = i >> 4, c4 = (i & 15) << 2;
            size_t gidx = ((size_t)bh * LL + key0 + t0 + r) * DD + c4;
            *(float4*)&Ks[r * 68 + c4] = *(const float4*)&g_K[gidx];
            *(float4*)&Vs[r * 64 + c4] = *(const float4*)&g_V[gidx];
        }
        __syncthreads();

        float s[8];
#pragma unroll
        for (int tt = 0; tt < 8; tt++) {
            int j = lane8 + 8 * tt;
            const float* kr = Ks + j * 68;
            float sv = 0.f;
#pragma unroll
            for (int dd = 0; dd < 16; dd++) {
                float4 kv = *(const float4*)(kr + dd * 4);
                sv += q4[dd].x * kv.x + q4[dd].y * kv.y +
                      q4[dd].z * kv.z + q4[dd].w * kv.w;
            }
            s[tt] = sv * SCALE;
        }
        float tmax = s[0];
#pragma unroll
        for (int tt = 1; tt < 8; tt++) tmax = fmaxf(tmax, s[tt]);
#pragma unroll
        for (int off = 4; off; off >>= 1)
            tmax = fmaxf(tmax, __shfl_xor_sync(0xffffffffu, tmax, off));
        float mnew = fmaxf(m, tmax);
        float alpha = __expf(m - mnew);
        lsum *= alpha;
#pragma unroll
        for (int i = 0; i < 8; i++) acc[i] *= alpha;
        float p[8];
#pragma unroll
        for (int tt = 0; tt < 8; tt++) {
            p[tt] = __expf(s[tt] - mnew);
            lsum += p[tt];
        }
        m = mnew;
#pragma unroll
        for (int j = 0; j < 64; j++) {
            float pj = __shfl_sync(0xffffffffu, p[j >> 3], j & 7, 8);
            const float* vr = Vs + j * 64 + lane8 * 8;
            float4 v0 = *(const float4*)vr;
            float4 v1 = *(const float4*)(vr + 4);
            acc[0] += pj * v0.x; acc[1] += pj * v0.y;
            acc[2] += pj * v0.z; acc[3] += pj * v0.w;
            acc[4] += pj * v1.x; acc[5] += pj * v1.y;
            acc[6] += pj * v1.z; acc[7] += pj * v1.w;
        }
    }
#pragma unroll
    for (int off = 4; off; off >>= 1)
        lsum += __shfl_xor_sync(0xffffffffu, lsum, off);

    if (q < UU) {
        int idx = (bh * NCH + ch) * UU + q;
        if (lane8 == 0) { g_pm[idx] = m; g_pl[idx] = lsum; }
        float* pa = g_pacc + (size_t)idx * DD + lane8 * 8;
#pragma unroll
        for (int i = 0; i < 8; i++) pa[i] = acc[i];
    }
}

// ---------------- merge split-L partials ----------------
__global__ __launch_bounds__(64) void combine_kernel()
{
    int r = blockIdx.x;
    int d = threadIdx.x;
    int bh = r / UU, q = r % UU;
    float M = -1e30f;
#pragma unroll
    for (int c = 0; c < NCH; c++)
        M = fmaxf(M, g_pm[(bh * NCH + c) * UU + q]);
    float Ltot = 0.f, acc = 0.f;
#pragma unroll
    for (int c = 0; c < NCH; c++) {
        int idx = (bh * NCH + c) * UU + q;
        float e = __expf(g_pm[idx] - M);
        Ltot += g_pl[idx] * e;
        acc  += e * g_pacc[(size_t)idx * DD + d];
    }
    g_attn[(size_t)(bh * UU + q) * DD + d] = acc / Ltot;
}

// ---------------- final output: broadcast base row + rank-64 head corrections ----------------
__global__ __launch_bounds__(128) void final_kernel(const float* __restrict__ Wo,
                                                    float* __restrict__ out)
{
    __shared__ int s_hits[HH];
    __shared__ float delta[64];
    int qrow = blockIdx.x, b = blockIdx.y;
    int tid = threadIdx.x;
    int c0 = tid * 4;

    if (tid < HH) s_hits[tid] = -1;
    __syncthreads();
    if (tid < UU) {
#pragma unroll
        for (int h = 0; h < HH; h++)
            if (g_top[(b * HH + h) * UU + tid] == qrow) s_hits[h] = tid;
    }
    __syncthreads();

    float4 acc = *(const float4*)&g_base[b * DM + c0];
    for (int h = 0; h < HH; h++) {
        int hit = s_hits[h];
        if (hit >= 0) {
            if (tid < 64)
                delta[tid] = g_attn[((size_t)(b * HH + h) * UU + hit) * DD + tid] -
                             g_meanV[(b * HH + h) * DD + tid];
            __syncthreads();
#pragma unroll 4
            for (int d = 0; d < 64; d++) {
                float dv = delta[d];
                float4 w = *(const float4*)&Wo[(size_t)(h * 64 + d) * DM + c0];
                acc.x += dv * w.x; acc.y += dv * w.y;
                acc.z += dv * w.z; acc.w += dv * w.w;
            }
            __syncthreads();
        }
    }
    *(float4*)&out[((size_t)b * LL + qrow) * DM + c0] = acc;
}

// ---------------- launcher ----------------
extern "C" void kernel_launch(void* const* d_in, const int* in_sizes, int n_in,
                              void* d_out, int out_size)
{
    const float* queries = (const float*)d_in[0];
    const float* keys    = (const float*)d_in[1];
    const float* values  = (const float*)d_in[2];
    const int*   sidx    = (const int*)d_in[3];
    const float* Wq = (const float*)d_in[4];
    const float* bq = (const float*)d_in[5];
    const float* Wk = (const float*)d_in[6];
    const float* bk = (const float*)d_in[7];
    const float* Wv = (const float*)d_in[8];
    const float* bv = (const float*)d_in[9];
    const float* Wo = (const float*)d_in[10];
    const float* bo = (const float*)d_in[11];
    float* out = (float*)d_out;

    static int smem_set = 0;
    if (!smem_set) {
        cudaFuncSetAttribute(proj_mma, cudaFuncAttributeMaxDynamicSharedMemorySize, DYN_SMEM);
        smem_set = 1;
    }

    prep_w<<<dim3(256, 3), 256>>>(Wq, Wk, Wv);
    split_act<<<dim3(BL * DM / (256 * 8), 3), 256>>>(queries, keys, values);

    proj_mma<<<dim3(DM / 128, BL / 128, 3), 256, DYN_SMEM>>>(bq, bk, bv);

    score_kernel<<<dim3(BB * HH, LL / 128), 256>>>(sidx);
    topk_kernel<<<BB * HH, 256>>>();
    meanv_kernel<<<BB * HH, 256>>>();
    base_kernel<<<BB, 512>>>(Wo, bo);
    att_kernel<<<dim3(BB * HH, NCH), 384>>>();
    combine_kernel<<<BB * HH * UU, 64>>>();
    final_kernel<<<dim3(LL, BB), 128>>>(Wo, out);
}

// round 4
// speedup vs baseline: 2.0014x; 1.0747x over previous
#include <cuda_runtime.h>
#include <cuda_bf16.h>
#include <cstdint>

#define BB 8
#define LL 4096
#define DM 512
#define HH 8
#define DD 64
#define UU 45
#define NCH 16
#define CHUNK (LL / NCH)
#define SCALE 0.125f
#define BL (BB * LL)

// ---------------- scratch (static device globals; no allocs allowed) ----------------
__device__ float g_Q[BB * HH * LL * DD];
__device__ float g_K[BB * HH * LL * DD];
__device__ float g_V[BB * HH * LL * DD];
__device__ float g_M[BB * HH * LL];
__device__ int   g_top[BB * HH * UU];
__device__ float g_meanV[BB * HH * DD];
__device__ float g_base[BB * DM];
__device__ float g_pm[BB * HH * NCH * UU];
__device__ float g_pl[BB * HH * NCH * UU];
__device__ float g_pacc[BB * HH * NCH * UU * DD];
__device__ float g_attn[BB * HH * UU * DD];
__device__ __nv_bfloat16 g_Wth[3][DM * DM];   // W transposed [n][k], hi bf16
__device__ __nv_bfloat16 g_Wtl[3][DM * DM];   // W transposed [n][k], lo bf16
__device__ __nv_bfloat16 g_Ah[3][BL * DM];    // activations hi bf16
__device__ __nv_bfloat16 g_Al[3][BL * DM];    // activations lo bf16

// ================= PTX helpers (sm_80-era, legal on sm_103 base) =================
__device__ __forceinline__ uint32_t smem_u32(const void* p) {
    uint32_t a;
    asm("{ .reg .u64 t; cvta.to.shared.u64 t, %1; cvt.u32.u64 %0, t; }"
        : "=r"(a) : "l"(p));
    return a;
}
#define SWZ128(off)   ((off) ^ (((off) >> 3) & 0x70))

#define CP_ASYNC16(dst, src) \
    asm volatile("cp.async.cg.shared.global [%0], [%1], 16;" :: "r"(dst), "l"(src))
#define CP_COMMIT() asm volatile("cp.async.commit_group;" ::: "memory")
#define CP_WAIT(n)  asm volatile("cp.async.wait_group %0;" :: "n"(n) : "memory")

__device__ __forceinline__ void ldsm_x4(uint32_t* r, uint32_t addr) {
    asm volatile("ldmatrix.sync.aligned.m8n8.x4.shared.b16 {%0,%1,%2,%3}, [%4];"
        : "=r"(r[0]), "=r"(r[1]), "=r"(r[2]), "=r"(r[3]) : "r"(addr));
}
__device__ __forceinline__ void mma16816(float* d, const uint32_t* a,
                                         const uint32_t* b, const float* c) {
    asm volatile(
        "mma.sync.aligned.m16n8k16.row.col.f32.bf16.bf16.f32 "
        "{%0,%1,%2,%3},{%4,%5,%6,%7},{%8,%9},{%10,%11,%12,%13};"
        : "=f"(d[0]), "=f"(d[1]), "=f"(d[2]), "=f"(d[3])
        : "r"(a[0]), "r"(a[1]), "r"(a[2]), "r"(a[3]),
          "r"(b[0]), "r"(b[1]),
          "f"(c[0]), "f"(c[1]), "f"(c[2]), "f"(c[3]));
}

// smem stage layout: 4 tiles of 128x64 bf16 (16KB each), 2 stages
#define T_AH 0
#define T_AL 16384
#define T_WH 32768
#define T_WL 49152
#define STAGE_SZ 65536
#define OFF_BIAS 131072
#define DYN_SMEM (131072 + 1024)

// ---------------- W prep: transpose + split to bf16 hi/lo ----------------
__global__ __launch_bounds__(256) void prep_w(const float* __restrict__ Wq,
                                              const float* __restrict__ Wk,
                                              const float* __restrict__ Wv)
{
    int which = blockIdx.y;
    const float* W = (which == 0) ? Wq : (which == 1) ? Wk : Wv;
    int idx = (blockIdx.x * 256 + threadIdx.x) * 4;   // 4 consecutive k for fixed n
    int n = idx >> 9, k = idx & 511;
#pragma unroll
    for (int i = 0; i < 4; i++) {
        float x = W[(size_t)(k + i) * DM + n];
        __nv_bfloat16 hb = __float2bfloat16(x);
        g_Wth[which][(size_t)n * DM + k + i] = hb;
        g_Wtl[which][(size_t)n * DM + k + i] = __float2bfloat16(x - __bfloat162float(hb));
    }
}

// ---------------- activation split: fp32 -> bf16 hi/lo ----------------
__global__ __launch_bounds__(256) void split_act(const float* __restrict__ q,
                                                 const float* __restrict__ k,
                                                 const float* __restrict__ v)
{
    int which = blockIdx.y;
    const float* A = (which == 0) ? q : (which == 1) ? k : v;
    size_t i0 = ((size_t)blockIdx.x * 256 + threadIdx.x) * 8;
    float4 f0 = *(const float4*)(A + i0);
    float4 f1 = *(const float4*)(A + i0 + 4);
    float xs[8] = {f0.x, f0.y, f0.z, f0.w, f1.x, f1.y, f1.z, f1.w};
    __align__(16) __nv_bfloat16 h[8], l[8];
#pragma unroll
    for (int i = 0; i < 8; i++) {
        __nv_bfloat16 hb = __float2bfloat16(xs[i]);
        h[i] = hb;
        l[i] = __float2bfloat16(xs[i] - __bfloat162float(hb));
    }
    *(uint4*)&g_Ah[which][i0] = *(uint4*)h;
    *(uint4*)&g_Al[which][i0] = *(uint4*)l;
}

// ---------------- split-bf16 mma.sync GEMM: P = A x W + bias ----------------
__global__ __launch_bounds__(256) void proj_mma(
    const float* __restrict__ bq, const float* __restrict__ bk,
    const float* __restrict__ bv)
{
    extern __shared__ char dsm[];
    int which = blockIdx.z;
    float* P = (which == 0) ? g_Q : (which == 1) ? g_K : g_V;
    const float* bias = (which == 0) ? bq : (which == 1) ? bk : bv;
    const __nv_bfloat16* Ah = g_Ah[which];
    const __nv_bfloat16* Al = g_Al[which];
    const __nv_bfloat16* Wh = g_Wth[which];
    const __nv_bfloat16* Wl = g_Wtl[which];

    uint32_t su = smem_u32(dsm);
    int tid = threadIdx.x;
    int lane = tid & 31, wid = tid >> 5;
    int wm = wid & 3, wn = wid >> 2;          // warp: 32 M x 64 N
    int m0 = blockIdx.y * 128, n0 = blockIdx.x * 128;

    // bias slice -> smem
    float* bias_s = (float*)(dsm + OFF_BIAS);
    if (tid < 128) bias_s[tid] = bias[n0 + tid];

    float acc[2][8][4];
#pragma unroll
    for (int a = 0; a < 2; a++)
#pragma unroll
        for (int b = 0; b < 8; b++)
#pragma unroll
            for (int c = 0; c < 4; c++) acc[a][b][c] = 0.f;

    // --------- stage loader (cp.async) ---------
    auto load_stage = [&](int stage, int k0) {
        uint32_t sb = su + stage * STAGE_SZ;
#pragma unroll
        for (int t = 0; t < 4; t++) {
            int idx = tid + 256 * t;          // [0,1024)
            int r = idx >> 3, c = idx & 7;
            uint32_t sw = SWZ128((uint32_t)(r * 128 + c * 16));
            const __nv_bfloat16* asrc = Ah + (size_t)(m0 + r) * DM + k0 + c * 8;
            const __nv_bfloat16* lsrc = Al + (size_t)(m0 + r) * DM + k0 + c * 8;
            const __nv_bfloat16* wsrc = Wh + (size_t)(n0 + r) * DM + k0 + c * 8;
            const __nv_bfloat16* msrc = Wl + (size_t)(n0 + r) * DM + k0 + c * 8;
            CP_ASYNC16(sb + T_AH + sw, asrc);
            CP_ASYNC16(sb + T_AL + sw, lsrc);
            CP_ASYNC16(sb + T_WH + sw, wsrc);
            CP_ASYNC16(sb + T_WL + sw, msrc);
        }
        CP_COMMIT();
    };

    load_stage(0, 0);

    // precomputed ldsm base offsets (within a tile)
    int a_row = (lane & 15), a_k16 = (lane >> 4) << 4;
    int b_grp = lane >> 3;
    int b_row = ((b_grp >> 1) << 3) + (lane & 7);
    int b_k16 = (b_grp & 1) << 4;

    for (int chunk = 0; chunk < 8; chunk++) {
        if (chunk < 7) load_stage((chunk + 1) & 1, (chunk + 1) * 64);
        if (chunk < 7) { CP_WAIT(1); } else { CP_WAIT(0); }
        __syncthreads();

        uint32_t sb = su + (chunk & 1) * STAGE_SZ;
#pragma unroll
        for (int ks = 0; ks < 4; ks++) {
            // ---- load all fragments once per k-step ----
            uint32_t ah[2][4], al[2][4], bh[16], bl[16];
#pragma unroll
            for (int mf = 0; mf < 2; mf++) {
                int row = wm * 32 + mf * 16 + a_row;
                uint32_t off = SWZ128((uint32_t)(row * 128 + ks * 32 + a_k16));
                ldsm_x4(ah[mf], sb + T_AH + off);
                ldsm_x4(al[mf], sb + T_AL + off);
            }
#pragma unroll
            for (int g2 = 0; g2 < 4; g2++) {
                int row = wn * 64 + g2 * 16 + b_row;
                uint32_t off = SWZ128((uint32_t)(row * 128 + ks * 32 + b_k16));
                ldsm_x4(&bh[g2 * 4], sb + T_WH + off);
                ldsm_x4(&bl[g2 * 4], sb + T_WL + off);
            }
            // ---- 48 HMMA sharing the fragments ----
#pragma unroll
            for (int mf = 0; mf < 2; mf++)
#pragma unroll
                for (int nf = 0; nf < 8; nf++)
                    mma16816(acc[mf][nf], ah[mf], &bh[nf * 2], acc[mf][nf]);
#pragma unroll
            for (int mf = 0; mf < 2; mf++)
#pragma unroll
                for (int nf = 0; nf < 8; nf++)
                    mma16816(acc[mf][nf], ah[mf], &bl[nf * 2], acc[mf][nf]);
#pragma unroll
            for (int mf = 0; mf < 2; mf++)
#pragma unroll
                for (int nf = 0; nf < 8; nf++)
                    mma16816(acc[mf][nf], al[mf], &bh[nf * 2], acc[mf][nf]);
        }
        __syncthreads();
    }

    // --------- epilogue: frags -> smem (stride 132) -> coalesced scatter ---------
    float* Cs = (float*)dsm;
#pragma unroll
    for (int mf = 0; mf < 2; mf++)
#pragma unroll
        for (int nf = 0; nf < 8; nf++) {
            int r = wm * 32 + mf * 16 + (lane >> 2);
            int col = wn * 64 + nf * 8 + (lane & 3) * 2;
            Cs[r * 132 + col]           = acc[mf][nf][0] + bias_s[col];
            Cs[r * 132 + col + 1]       = acc[mf][nf][1] + bias_s[col + 1];
            Cs[(r + 8) * 132 + col]     = acc[mf][nf][2] + bias_s[col];
            Cs[(r + 8) * 132 + col + 1] = acc[mf][nf][3] + bias_s[col + 1];
        }
    __syncthreads();

#pragma unroll
    for (int it = 0; it < 16; it++) {
        int idx = tid + it * 256;            // [0,4096) float4 slots
        int row = idx >> 5, c4 = idx & 31;
        int m = m0 + row;
        int b = m >> 12, l = m & (LL - 1);
        int n = n0 + c4 * 4;
        int h = n >> 6, d = n & 63;
        float4 v;
        v.x = Cs[row * 132 + c4 * 4 + 0];
        v.y = Cs[row * 132 + c4 * 4 + 1];
        v.z = Cs[row * 132 + c4 * 4 + 2];
        v.w = Cs[row * 132 + c4 * 4 + 3];
        *(float4*)&P[((size_t)(b * HH + h) * LL + l) * DD + d] = v;
    }
}

// ---------------- sampled scoring: one thread per query, s[45] in regs ----------------
__global__ __launch_bounds__(128) void score_kernel(const int* __restrict__ sidx)
{
    __shared__ float Ks[UU * DD];         // 45 x 64
    __shared__ float Qt[DD * 129];        // transposed Q tile [d][qi], stride 129
    __shared__ int ssi[UU];
    int bh = blockIdx.x;
    int tid = threadIdx.x;
    if (tid < UU) ssi[tid] = sidx[tid];
    __syncthreads();
    for (int i = tid; i < UU * 16; i += 128) {   // 45*16 float4
        int j = i >> 4, c4 = i & 15;
        *(float4*)&Ks[j * 64 + c4 * 4] =
            *(const float4*)&g_K[((size_t)bh * LL + ssi[j]) * DD + c4 * 4];
    }
    int l0 = blockIdx.y * 128;
    // stage Q transposed: read coalesced float4, scatter to Qt[d][qi]
#pragma unroll
    for (int it = 0; it < 16; it++) {
        int idx = tid + it * 128;            // [0,2048) float4 slots
        int qi = idx >> 4, c4 = idx & 15;
        float4 v = *(const float4*)&g_Q[((size_t)bh * LL + l0 + qi) * DD + c4 * 4];
        Qt[(c4 * 4 + 0) * 129 + qi] = v.x;
        Qt[(c4 * 4 + 1) * 129 + qi] = v.y;
        Qt[(c4 * 4 + 2) * 129 + qi] = v.z;
        Qt[(c4 * 4 + 3) * 129 + qi] = v.w;
    }
    __syncthreads();

    float s[UU];
#pragma unroll
    for (int j = 0; j < UU; j++) s[j] = 0.f;

    int qi = tid;
    for (int c = 0; c < DD; c += 4) {
        float q0 = Qt[(c + 0) * 129 + qi];
        float q1 = Qt[(c + 1) * 129 + qi];
        float q2 = Qt[(c + 2) * 129 + qi];
        float q3 = Qt[(c + 3) * 129 + qi];
#pragma unroll
        for (int j = 0; j < UU; j++) {
            float4 k4 = *(const float4*)&Ks[j * 64 + c];
            s[j] += q0 * k4.x + q1 * k4.y + q2 * k4.z + q3 * k4.w;
        }
    }

    float mx = s[0], sm = s[0];
#pragma unroll
    for (int j = 1; j < UU; j++) {
        mx = fmaxf(mx, s[j]);
        sm += s[j];
    }
    g_M[(size_t)bh * LL + l0 + qi] = (mx - sm * (1.f / UU)) * SCALE;
}

// ---------------- top-45 selection per (b,h) ----------------
__global__ __launch_bounds__(256) void topk_kernel()
{
    __shared__ float vals[LL];
    __shared__ float rv[256];
    __shared__ int ri[256];
    int bh = blockIdx.x, tid = threadIdx.x;
    for (int i = tid; i < LL; i += 256) vals[i] = g_M[(size_t)bh * LL + i];
    __syncthreads();
    for (int it = 0; it < UU; it++) {
        float bv = -1e38f; int bi = 0x7fffffff;
        for (int i = tid; i < LL; i += 256) {
            float v = vals[i];
            if (v > bv) { bv = v; bi = i; }
        }
        rv[tid] = bv; ri[tid] = bi;
        __syncthreads();
        for (int s = 128; s > 0; s >>= 1) {
            if (tid < s) {
                float v2 = rv[tid + s]; int i2 = ri[tid + s];
                if (v2 > rv[tid] || (v2 == rv[tid] && i2 < ri[tid])) {
                    rv[tid] = v2; ri[tid] = i2;
                }
            }
            __syncthreads();
        }
        if (tid == 0) {
            g_top[bh * UU + it] = ri[0];
            vals[ri[0]] = -1e38f;
        }
        __syncthreads();
    }
}

// ---------------- mean(V) over L per (b,h,d) ----------------
__global__ __launch_bounds__(256) void meanv_kernel()
{
    __shared__ float red[4][64];
    int bh = blockIdx.x, tid = threadIdx.x;
    int d = tid & 63, part = tid >> 6;
    const float* base = g_V + ((size_t)bh * LL + part * (LL / 4)) * DD + d;
    float s0 = 0.f, s1 = 0.f, s2 = 0.f, s3 = 0.f;
    for (int i = 0; i < LL / 4; i += 4) {
        s0 += base[(size_t)(i + 0) * DD];
        s1 += base[(size_t)(i + 1) * DD];
        s2 += base[(size_t)(i + 2) * DD];
        s3 += base[(size_t)(i + 3) * DD];
    }
    red[part][d] = (s0 + s1) + (s2 + s3);
    __syncthreads();
    if (part == 0)
        g_meanV[bh * DD + d] =
            (red[0][d] + red[1][d] + red[2][d] + red[3][d]) * (1.f / LL);
}

// ---------------- base row per batch: concat(meanV) @ Wo + bo ----------------
__global__ __launch_bounds__(512) void base_kernel(const float* __restrict__ Wo,
                                                   const float* __restrict__ bo)
{
    int b = blockIdx.x, c = threadIdx.x;
    float acc = bo[c];
    const float* mv = g_meanV + b * DM;
    for (int k = 0; k < DM; k++) acc += mv[k] * Wo[(size_t)k * DM + c];
    g_base[b * DM + c] = acc;
}

// ---------------- flash attention for top-45 queries, split over NCH L-chunks ----------------
__global__ __launch_bounds__(384) void att_kernel()
{
    __shared__ float Qs[UU * 64];
    __shared__ float Ks[64 * 68];
    __shared__ float Vs[64 * 64];
    int bh = blockIdx.x, ch = blockIdx.y;
    int tid = threadIdx.x;
    int q = tid >> 3, lane8 = tid & 7;
    int qe = (q < UU) ? q : (UU - 1);

    for (int i = tid; i < UU * 64; i += 384) {
        int qq = i >> 6, d = i & 63;
        int l = g_top[bh * UU + qq];
        Qs[i] = g_Q[((size_t)bh * LL + l) * DD + d];
    }
    __syncthreads();

    float4 q4[16];
#pragma unroll
    for (int dd = 0; dd < 16; dd++) q4[dd] = *(const float4*)(Qs + qe * 64 + dd * 4);

    float m = -1e30f, lsum = 0.f;
    float acc[8];
#pragma unroll
    for (int i = 0; i < 8; i++) acc[i] = 0.f;

    int key0 = ch * CHUNK;
    for (int t0 = 0; t0 < CHUNK; t0 += 64) {
        __syncthreads();
        for (int i = tid; i < 1024; i += 384) {
            int r = i >> 4, c4 = (i & 15) << 2;
            size_t gidx = ((size_t)bh * LL + key0 + t0 + r) * DD + c4;
            *(float4*)&Ks[r * 68 + c4] = *(const float4*)&g_K[gidx];
            *(float4*)&Vs[r * 64 + c4] = *(const float4*)&g_V[gidx];
        }
        __syncthreads();

        float s[8];
#pragma unroll
        for (int tt = 0; tt < 8; tt++) {
            int j = lane8 + 8 * tt;
            const float* kr = Ks + j * 68;
            float sv = 0.f;
#pragma unroll
            for (int dd = 0; dd < 16; dd++) {
                float4 kv = *(const float4*)(kr + dd * 4);
                sv += q4[dd].x * kv.x + q4[dd].y * kv.y +
                      q4[dd].z * kv.z + q4[dd].w * kv.w;
            }
            s[tt] = sv * SCALE;
        }
        float tmax = s[0];
#pragma unroll
        for (int tt = 1; tt < 8; tt++) tmax = fmaxf(tmax, s[tt]);
#pragma unroll
        for (int off = 4; off; off >>= 1)
            tmax = fmaxf(tmax, __shfl_xor_sync(0xffffffffu, tmax, off));
        float mnew = fmaxf(m, tmax);
        float alpha = __expf(m - mnew);
        lsum *= alpha;
#pragma unroll
        for (int i = 0; i < 8; i++) acc[i] *= alpha;
        float p[8];
#pragma unroll
        for (int tt = 0; tt < 8; tt++) {
            p[tt] = __expf(s[tt] - mnew);
            lsum += p[tt];
        }
        m = mnew;
#pragma unroll
        for (int j = 0; j < 64; j++) {
            float pj = __shfl_sync(0xffffffffu, p[j >> 3], j & 7, 8);
            const float* vr = Vs + j * 64 + lane8 * 8;
            float4 v0 = *(const float4*)vr;
            float4 v1 = *(const float4*)(vr + 4);
            acc[0] += pj * v0.x; acc[1] += pj * v0.y;
            acc[2] += pj * v0.z; acc[3] += pj * v0.w;
            acc[4] += pj * v1.x; acc[5] += pj * v1.y;
            acc[6] += pj * v1.z; acc[7] += pj * v1.w;
        }
    }
#pragma unroll
    for (int off = 4; off; off >>= 1)
        lsum += __shfl_xor_sync(0xffffffffu, lsum, off);

    if (q < UU) {
        int idx = (bh * NCH + ch) * UU + q;
        if (lane8 == 0) { g_pm[idx] = m; g_pl[idx] = lsum; }
        float* pa = g_pacc + (size_t)idx * DD + lane8 * 8;
#pragma unroll
        for (int i = 0; i < 8; i++) pa[i] = acc[i];
    }
}

// ---------------- merge split-L partials ----------------
__global__ __launch_bounds__(64) void combine_kernel()
{
    int r = blockIdx.x;
    int d = threadIdx.x;
    int bh = r / UU, q = r % UU;
    float M = -1e30f;
#pragma unroll
    for (int c = 0; c < NCH; c++)
        M = fmaxf(M, g_pm[(bh * NCH + c) * UU + q]);
    float Ltot = 0.f, acc = 0.f;
#pragma unroll
    for (int c = 0; c < NCH; c++) {
        int idx = (bh * NCH + c) * UU + q;
        float e = __expf(g_pm[idx] - M);
        Ltot += g_pl[idx] * e;
        acc  += e * g_pacc[(size_t)idx * DD + d];
    }
    g_attn[(size_t)(bh * UU + q) * DD + d] = acc / Ltot;
}

// ---------------- final output: broadcast base row + rank-64 head corrections ----------------
__global__ __launch_bounds__(128) void final_kernel(const float* __restrict__ Wo,
                                                    float* __restrict__ out)
{
    __shared__ int s_hits[HH];
    __shared__ float delta[64];
    int qrow = blockIdx.x, b = blockIdx.y;
    int tid = threadIdx.x;
    int c0 = tid * 4;

    if (tid < HH) s_hits[tid] = -1;
    __syncthreads();
    if (tid < UU) {
#pragma unroll
        for (int h = 0; h < HH; h++)
            if (g_top[(b * HH + h) * UU + tid] == qrow) s_hits[h] = tid;
    }
    __syncthreads();

    float4 acc = *(const float4*)&g_base[b * DM + c0];
    for (int h = 0; h < HH; h++) {
        int hit = s_hits[h];
        if (hit >= 0) {
            if (tid < 64)
                delta[tid] = g_attn[((size_t)(b * HH + h) * UU + hit) * DD + tid] -
                             g_meanV[(b * HH + h) * DD + tid];
            __syncthreads();
#pragma unroll 4
            for (int d = 0; d < 64; d++) {
                float dv = delta[d];
                float4 w = *(const float4*)&Wo[(size_t)(h * 64 + d) * DM + c0];
                acc.x += dv * w.x; acc.y += dv * w.y;
                acc.z += dv * w.z; acc.w += dv * w.w;
            }
            __syncthreads();
        }
    }
    *(float4*)&out[((size_t)b * LL + qrow) * DM + c0] = acc;
}

// ---------------- launcher ----------------
extern "C" void kernel_launch(void* const* d_in, const int* in_sizes, int n_in,
                              void* d_out, int out_size)
{
    const float* queries = (const float*)d_in[0];
    const float* keys    = (const float*)d_in[1];
    const float* values  = (const float*)d_in[2];
    const int*   sidx    = (const int*)d_in[3];
    const float* Wq = (const float*)d_in[4];
    const float* bq = (const float*)d_in[5];
    const float* Wk = (const float*)d_in[6];
    const float* bk = (const float*)d_in[7];
    const float* Wv = (const float*)d_in[8];
    const float* bv = (const float*)d_in[9];
    const float* Wo = (const float*)d_in[10];
    const float* bo = (const float*)d_in[11];
    float* out = (float*)d_out;

    static int smem_set = 0;
    if (!smem_set) {
        cudaFuncSetAttribute(proj_mma, cudaFuncAttributeMaxDynamicSharedMemorySize, DYN_SMEM);
        smem_set = 1;
    }

    prep_w<<<dim3(256, 3), 256>>>(Wq, Wk, Wv);
    split_act<<<dim3(BL * DM / (256 * 8), 3), 256>>>(queries, keys, values);

    proj_mma<<<dim3(DM / 128, BL / 128, 3), 256, DYN_SMEM>>>(bq, bk, bv);

    score_kernel<<<dim3(BB * HH, LL / 128), 128>>>(sidx);
    topk_kernel<<<BB * HH, 256>>>();
    meanv_kernel<<<BB * HH, 256>>>();
    base_kernel<<<BB, 512>>>(Wo, bo);
    att_kernel<<<dim3(BB * HH, NCH), 384>>>();
    combine_kernel<<<BB * HH * UU, 64>>>();
    final_kernel<<<dim3(LL, BB), 128>>>(Wo, out);
}